// round 2
// baseline (speedup 1.0000x reference)
#include <cuda_runtime.h>

#define L_PTS 256
#define WARPS_PER_BLOCK 8
#define N_PTS_MAX 2000000

// 32MB packed scratch: (x, y, z, bits(v)&~7 | sem)
__device__ float4 g_packed[N_PTS_MAX];

__global__ void __launch_bounds__(256)
pack_kernel(const float* __restrict__ data, int n_pts)
{
    int t = blockIdx.x * blockDim.x + threadIdx.x;   // one thread per PAIR of rows
    int r0i = 2 * t;
    if (r0i >= n_pts) return;
    const float4* d4 = reinterpret_cast<const float4*>(data);
    // rows 2t and 2t+1 occupy 48B = 3 aligned float4
    float4 q0 = d4[3 * t];
    float4 q1 = d4[3 * t + 1];
    // row even: x,y,z,b = q0 ; v,s = q1.x,q1.y
    {
        unsigned vb = (__float_as_uint(q1.x) & ~7u) | ((unsigned)q1.y & 7u);
        g_packed[r0i] = make_float4(q0.x, q0.y, q0.z, __uint_as_float(vb));
    }
    if (r0i + 1 < n_pts) {
        float4 q2 = d4[3 * t + 2];
        // row odd: x,y = q1.z,q1.w ; z,b = q2.x,q2.y ; v,s = q2.z,q2.w
        unsigned vb = (__float_as_uint(q2.z) & ~7u) | ((unsigned)q2.w & 7u);
        g_packed[r0i + 1] = make_float4(q1.z, q1.w, q2.x, __uint_as_float(vb));
    }
}

__device__ __forceinline__ float wredf(float v) {
#pragma unroll
    for (int o = 16; o; o >>= 1) v += __shfl_xor_sync(0xffffffffu, v, o);
    return v;
}
__device__ __forceinline__ int wredi(int v) {
#pragma unroll
    for (int o = 16; o; o >>= 1) v += __shfl_xor_sync(0xffffffffu, v, o);
    return v;
}

__global__ void __launch_bounds__(256)
clust_geo_kernel(const int* __restrict__ clust_idx,
                 const int* __restrict__ clust_len,
                 float* __restrict__ out,
                 int n_clust)
{
    const int warp = threadIdx.x >> 5;
    const int lane = threadIdx.x & 31;
    const int c = blockIdx.x * WARPS_PER_BLOCK + warp;
    if (c >= n_clust) return;

    const int len = clust_len[c];

    // --- load 8 indices per lane (contiguous chunk, int4 coalesced) ---
    const int4* ci = reinterpret_cast<const int4*>(clust_idx + (size_t)c * L_PTS) + lane * 2;
    int4 i0 = ci[0];
    int4 i1 = ci[1];
    int idx[8] = { i0.x, i0.y, i0.z, i0.w, i1.x, i1.y, i1.z, i1.w };

    const int base_pt = lane * 8;

    float px[8], py[8], pz[8];
    float sx = 0.f, sy = 0.f, sz = 0.f, sv = 0.f, svv = 0.f;
    int cA = 0, cB = 0;   // packed sem counts: cA = bins 0..2 (10 bits each), cB = bins 3..4

    // --- pass A: single aligned float4 gather per point ---
#pragma unroll
    for (int k = 0; k < 8; k++) {
        bool act = (base_pt + k) < len;
        float X = 0.f, Y = 0.f, Z = 0.f;
        if (act) {
            float4 q = g_packed[idx[k]];
            X = q.x; Y = q.y; Z = q.z;
            unsigned vb = __float_as_uint(q.w);
            int s = (int)(vb & 7u);
            float V = __uint_as_float(vb & ~7u);
            sx += X; sy += Y; sz += Z;
            sv += V; svv += V * V;
            if (s < 3) cA += 1 << (10 * s);
            else       cB += 1 << (10 * (s - 3));
        }
        px[k] = X; py[k] = Y; pz[k] = Z;
    }
    sx = wredf(sx); sy = wredf(sy); sz = wredf(sz);
    sv = wredf(sv); svv = wredf(svv);
    cA = wredi(cA); cB = wredi(cB);

    const float n = (float)len;
    const float invn = 1.0f / n;
    const float cx = sx * invn, cy = sy * invn, cz = sz * invn;

    // --- pass B: 3x3 scatter matrix (register-resident points) ---
    float axx = 0.f, axy = 0.f, axz = 0.f, ayy = 0.f, ayz = 0.f, azz = 0.f;
#pragma unroll
    for (int k = 0; k < 8; k++) {
        if ((base_pt + k) < len) {
            float X = px[k] - cx, Y = py[k] - cy, Z = pz[k] - cz;
            axx += X * X; axy += X * Y; axz += X * Z;
            ayy += Y * Y; ayz += Y * Z; azz += Z * Z;
        }
    }
    axx = wredf(axx); axy = wredf(axy); axz = wredf(axz);
    ayy = wredf(ayy); ayz = wredf(ayz); azz = wredf(azz);

    // --- analytic eigenvalues (Cardano), all lanes redundantly ---
    float q = (axx + ayy + azz) * (1.0f / 3.0f);
    float bxx = axx - q, byy = ayy - q, bzz = azz - q;
    float p1 = axy * axy + axz * axz + ayz * ayz;
    float p2 = bxx * bxx + byy * byy + bzz * bzz + 2.0f * p1;
    float w1, w2;
    if (p2 > 0.0f) {
        float p = sqrtf(p2 * (1.0f / 6.0f));
        float ip = 1.0f / p;
        float cxx = bxx * ip, cyy = byy * ip, czz = bzz * ip;
        float dxy = axy * ip, dxz = axz * ip, dyz = ayz * ip;
        float detB = cxx * (cyy * czz - dyz * dyz)
                   - dxy * (dxy * czz - dyz * dxz)
                   + dxz * (dxy * dyz - cyy * dxz);
        float r = 0.5f * detB;
        r = fminf(1.0f, fmaxf(-1.0f, r));
        float phi = acosf(r) * (1.0f / 3.0f);
        w2 = q + 2.0f * p * cosf(phi);
        float w0 = q + 2.0f * p * cosf(phi + 2.0943951023931953f);
        w1 = 3.0f * q - w0 - w2;
    } else {
        w1 = q; w2 = q;
    }

    // --- top eigenvector: largest cross product of rows of (A - w2 I) ---
    float mxx = axx - w2, myy = ayy - w2, mzz = azz - w2;
    float c0x = axy * ayz - axz * myy;     // r0 x r1
    float c0y = axz * axy - mxx * ayz;
    float c0z = mxx * myy - axy * axy;
    float c1x = axy * mzz - axz * ayz;     // r0 x r2
    float c1y = axz * axz - mxx * mzz;
    float c1z = mxx * ayz - axy * axz;
    float c2x = myy * mzz - ayz * ayz;     // r1 x r2
    float c2y = ayz * axz - axy * mzz;
    float c2z = axy * ayz - myy * axz;

    float n0 = c0x * c0x + c0y * c0y + c0z * c0z;
    float n1 = c1x * c1x + c1y * c1y + c1z * c1z;
    float n2 = c2x * c2x + c2y * c2y + c2z * c2z;
    float vx = c0x, vy = c0y, vz = c0z, nn = n0;
    if (n1 > nn) { vx = c1x; vy = c1y; vz = c1z; nn = n1; }
    if (n2 > nn) { vx = c2x; vy = c2y; vz = c2z; nn = n2; }
    if (nn > 0.0f) {
        float is = rsqrtf(nn);
        vx *= is; vy *= is; vz *= is;
    } else {
        vx = 0.0f; vy = 0.0f; vz = 1.0f;
    }

    // --- pass C: sign score ---
    float sc = 0.0f;
#pragma unroll
    for (int k = 0; k < 8; k++) {
        if ((base_pt + k) < len) {
            float X = px[k] - cx, Y = py[k] - cy, Z = pz[k] - cz;
            float x0 = X * vx + Y * vy + Z * vz;
            float sq = X * X + Y * Y + Z * Z - x0 * x0;
            sc += x0 * sqrtf(fmaxf(sq, 0.0f));
        }
    }
    sc = wredf(sc);

    float dirwt = (w2 == 0.0f) ? 0.0f : (1.0f - w1 / w2);
    float fac = ((sc < 0.0f) ? -1.0f : 1.0f) * dirwt;

    if (lane == 0) {
        float* o = out + (size_t)c * 19;
        float iw2 = 1.0f / w2;   // B = A / w2 exactly (DELTA = 0)
        o[0]  = cx; o[1] = cy; o[2] = cz;
        o[3]  = axx * iw2; o[4]  = axy * iw2; o[5]  = axz * iw2;
        o[6]  = axy * iw2; o[7]  = ayy * iw2; o[8]  = ayz * iw2;
        o[9]  = axz * iw2; o[10] = ayz * iw2; o[11] = azz * iw2;
        o[12] = vx * fac; o[13] = vy * fac; o[14] = vz * fac;
        o[15] = n;
        o[16] = sv * invn;
        float var = fmaxf(svv - sv * sv * invn, 0.0f) / (n - 1.0f);
        o[17] = sqrtf(var);
        int b0 = cA & 1023, b1 = (cA >> 10) & 1023, b2 = (cA >> 20) & 1023;
        int b3 = cB & 1023, b4 = (cB >> 10) & 1023;
        int best = b0, mode = 0;
        if (b1 > best) { best = b1; mode = 1; }
        if (b2 > best) { best = b2; mode = 2; }
        if (b3 > best) { best = b3; mode = 3; }
        if (b4 > best) { best = b4; mode = 4; }
        o[18] = (float)mode;
    }
}

extern "C" void kernel_launch(void* const* d_in, const int* in_sizes, int n_in,
                              void* d_out, int out_size) {
    const float* data      = (const float*)d_in[0];
    const int*   clust_idx = (const int*)d_in[1];
    const int*   clust_len = (const int*)d_in[2];
    float* out = (float*)d_out;
    int n_pts   = in_sizes[0] / 6;
    int n_clust = in_sizes[2];

    int pairs = (n_pts + 1) / 2;
    pack_kernel<<<(pairs + 255) / 256, 256>>>(data, n_pts);

    int grid = (n_clust + WARPS_PER_BLOCK - 1) / WARPS_PER_BLOCK;
    clust_geo_kernel<<<grid, 256>>>(clust_idx, clust_len, out, n_clust);
}

// round 3
// speedup vs baseline: 1.1616x; 1.1616x over previous
#include <cuda_runtime.h>

#define L_PTS 256
#define WPB 8   // warps (clusters) per block

__device__ __forceinline__ float wredf(float v) {
#pragma unroll
    for (int o = 16; o; o >>= 1) v += __shfl_xor_sync(0xffffffffu, v, o);
    return v;
}
__device__ __forceinline__ int wredi(int v) {
#pragma unroll
    for (int o = 16; o; o >>= 1) v += __shfl_xor_sync(0xffffffffu, v, o);
    return v;
}

__global__ void __launch_bounds__(256, 5)
clust_geo_kernel(const float* __restrict__ data,
                 const int* __restrict__ clust_idx,
                 const int* __restrict__ clust_len,
                 float* __restrict__ out,
                 int n_clust)
{
    __shared__ float spx[WPB][L_PTS];
    __shared__ float spy[WPB][L_PTS];
    __shared__ float spz[WPB][L_PTS];
    __shared__ float stage[WPB][19];

    const int warp = threadIdx.x >> 5;
    const int lane = threadIdx.x & 31;
    const int c = blockIdx.x * WPB + warp;
    const bool live = c < n_clust;

    int len = 2;  // dummy for dead warps (avoid inf paths)
    float sx = 0.f, sy = 0.f, sz = 0.f;
    float sxx = 0.f, sxy = 0.f, sxz = 0.f, syy = 0.f, syz = 0.f, szz = 0.f;
    float sv = 0.f, svv = 0.f;
    int cA = 0, cB = 0;   // packed sem counts: cA = bins 0..2 (10 bits each), cB = bins 3..4

    // --- pass A: gather + all first/second moment accumulation ---
    if (live) {
        len = clust_len[c];
        const float4* d4 = reinterpret_cast<const float4*>(data);
        const int* ci = clust_idx + (size_t)c * L_PTS + lane;   // stride-32 point mapping
#pragma unroll
        for (int k = 0; k < 8; k++) {
            const int pt = lane + 32 * k;
            const bool act = pt < len;
            float X = 0.f, Y = 0.f, Z = 0.f;
            if (act) {
                int id = ci[32 * k];
                int a = (id * 3) >> 1;        // float4 index of aligned base of 24B row
                float4 q0 = d4[a];
                float4 q1 = d4[a + 1];
                bool odd = (id & 1);
                X = odd ? q0.z : q0.x;
                Y = odd ? q0.w : q0.y;
                Z = odd ? q1.x : q0.z;
                float V = odd ? q1.z : q1.x;
                float S = odd ? q1.w : q1.y;
                sx += X; sy += Y; sz += Z;
                sxx += X * X; sxy += X * Y; sxz += X * Z;
                syy += Y * Y; syz += Y * Z; szz += Z * Z;
                sv += V; svv += V * V;
                int s = (int)S;
                if (s < 3) cA += 1 << (10 * s);
                else       cB += 1 << (10 * (s - 3));
            }
            spx[warp][pt] = X; spy[warp][pt] = Y; spz[warp][pt] = Z;
        }
    }

    sx = wredf(sx); sy = wredf(sy); sz = wredf(sz);
    sxx = wredf(sxx); sxy = wredf(sxy); sxz = wredf(sxz);
    syy = wredf(syy); syz = wredf(syz); szz = wredf(szz);
    sv = wredf(sv); svv = wredf(svv);
    cA = wredi(cA); cB = wredi(cB);

    const float n = (float)len;
    const float invn = 1.0f / n;
    const float cx = sx * invn, cy = sy * invn, cz = sz * invn;

    // shifted second moments: A = S2 - s1 * center
    const float axx = sxx - sx * cx, axy = sxy - sx * cy, axz = sxz - sx * cz;
    const float ayy = syy - sy * cy, ayz = syz - sy * cz, azz = szz - sz * cz;

    // --- analytic eigenvalues (Cardano), all lanes redundantly ---
    float q = (axx + ayy + azz) * (1.0f / 3.0f);
    float bxx = axx - q, byy = ayy - q, bzz = azz - q;
    float p1 = axy * axy + axz * axz + ayz * ayz;
    float p2 = bxx * bxx + byy * byy + bzz * bzz + 2.0f * p1;
    float w1, w2;
    if (p2 > 0.0f) {
        float p = sqrtf(p2 * (1.0f / 6.0f));
        float ip = 1.0f / p;
        float cxx = bxx * ip, cyy = byy * ip, czz = bzz * ip;
        float dxy = axy * ip, dxz = axz * ip, dyz = ayz * ip;
        float detB = cxx * (cyy * czz - dyz * dyz)
                   - dxy * (dxy * czz - dyz * dxz)
                   + dxz * (dxy * dyz - cyy * dxz);
        float r = 0.5f * detB;
        r = fminf(1.0f, fmaxf(-1.0f, r));
        float phi = acosf(r) * (1.0f / 3.0f);
        w2 = q + 2.0f * p * cosf(phi);
        float w0 = q + 2.0f * p * cosf(phi + 2.0943951023931953f);
        w1 = 3.0f * q - w0 - w2;
    } else {
        w1 = q; w2 = q;
    }

    // --- top eigenvector: largest cross product of rows of (A - w2 I) ---
    float mxx = axx - w2, myy = ayy - w2, mzz = azz - w2;
    float c0x = axy * ayz - axz * myy;
    float c0y = axz * axy - mxx * ayz;
    float c0z = mxx * myy - axy * axy;
    float c1x = axy * mzz - axz * ayz;
    float c1y = axz * axz - mxx * mzz;
    float c1z = mxx * ayz - axy * axz;
    float c2x = myy * mzz - ayz * ayz;
    float c2y = ayz * axz - axy * mzz;
    float c2z = axy * ayz - myy * axz;

    float n0 = c0x * c0x + c0y * c0y + c0z * c0z;
    float n1 = c1x * c1x + c1y * c1y + c1z * c1z;
    float n2 = c2x * c2x + c2y * c2y + c2z * c2z;
    float vx = c0x, vy = c0y, vz = c0z, nn = n0;
    if (n1 > nn) { vx = c1x; vy = c1y; vz = c1z; nn = n1; }
    if (n2 > nn) { vx = c2x; vy = c2y; vz = c2z; nn = n2; }
    if (nn > 0.0f) {
        float is = rsqrtf(nn);
        vx *= is; vy *= is; vz *= is;
    } else {
        vx = 0.0f; vy = 0.0f; vz = 1.0f;
    }

    // --- pass C: sign score (points from smem, conflict-free stride-32) ---
    float sc = 0.0f;
    if (live) {
#pragma unroll
        for (int k = 0; k < 8; k++) {
            const int pt = lane + 32 * k;
            if (pt < len) {
                float X = spx[warp][pt] - cx;
                float Y = spy[warp][pt] - cy;
                float Z = spz[warp][pt] - cz;
                float x0 = X * vx + Y * vy + Z * vz;
                float sq = X * X + Y * Y + Z * Z - x0 * x0;
                sc += x0 * sqrtf(fmaxf(sq, 0.0f));
            }
        }
    }
    sc = wredf(sc);

    float dirwt = (w2 == 0.0f) ? 0.0f : (1.0f - w1 / w2);
    float fac = ((sc < 0.0f) ? -1.0f : 1.0f) * dirwt;

    if (live && lane == 0) {
        float* st = stage[warp];
        float iw2 = 1.0f / w2;   // B = A / w2 exactly (DELTA = 0)
        st[0]  = cx; st[1] = cy; st[2] = cz;
        st[3]  = axx * iw2; st[4]  = axy * iw2; st[5]  = axz * iw2;
        st[6]  = axy * iw2; st[7]  = ayy * iw2; st[8]  = ayz * iw2;
        st[9]  = axz * iw2; st[10] = ayz * iw2; st[11] = azz * iw2;
        st[12] = vx * fac; st[13] = vy * fac; st[14] = vz * fac;
        st[15] = n;
        st[16] = sv * invn;
        float var = fmaxf(svv - sv * sv * invn, 0.0f) / (n - 1.0f);
        st[17] = sqrtf(var);
        int b0 = cA & 1023, b1 = (cA >> 10) & 1023, b2 = (cA >> 20) & 1023;
        int b3 = cB & 1023, b4 = (cB >> 10) & 1023;
        int best = b0, mode = 0;
        if (b1 > best) { best = b1; mode = 1; }
        if (b2 > best) { best = b2; mode = 2; }
        if (b3 > best) { best = b3; mode = 3; }
        if (b4 > best) { best = b4; mode = 4; }
        st[18] = (float)mode;
    }

    __syncthreads();

    // coalesced block output: clusters of this block are contiguous in out
    const int base = blockIdx.x * WPB;
    int nc = n_clust - base;
    if (nc > WPB) nc = WPB;
    const int tot = nc * 19;
    if ((int)threadIdx.x < tot)
        out[(size_t)base * 19 + threadIdx.x] = (&stage[0][0])[threadIdx.x];
}

extern "C" void kernel_launch(void* const* d_in, const int* in_sizes, int n_in,
                              void* d_out, int out_size) {
    const float* data      = (const float*)d_in[0];
    const int*   clust_idx = (const int*)d_in[1];
    const int*   clust_len = (const int*)d_in[2];
    float* out = (float*)d_out;
    int n_clust = in_sizes[2];
    int grid = (n_clust + WPB - 1) / WPB;
    clust_geo_kernel<<<grid, 256>>>(data, clust_idx, clust_len, out, n_clust);
}